// round 7
// baseline (speedup 1.0000x reference)
#include <cuda_runtime.h>
#include <math.h>

#define BB 8
#define CC 64
#define NN 4096
#define TOT (BB*CC*NN)
#define TILE_N 128
#define NTB (NN/TILE_N)      // 32 n-tiles per batch
#define TILES (BB*NTB)       // 256 blocks

typedef unsigned long long u64;

// Scratch (allocation-free: __device__ globals)
__device__ float g_z[TOT];                 // z = W @ x (8 MB)
__device__ float g_psum[BB*CC*NTB];        // partial Σz   [b][o][nb]
__device__ float g_psq [BB*CC*NTB];        // partial Σz²  [b][o][nb]
__device__ float g_spart[TILES];           // partial s_b  [b][nb]
__device__ float g_scale[BB*CC];
__device__ float g_bias [BB*CC];

// ---- f32x2 packed helpers (sm_103a) ----
__device__ __forceinline__ u64 ffma2(u64 a, u64 b, u64 c) {
    u64 d;
    asm("fma.rn.f32x2 %0, %1, %2, %3;" : "=l"(d) : "l"(a), "l"(b), "l"(c));
    return d;
}
__device__ __forceinline__ u64 packdup(float v) {
    u64 r;
    asm("mov.b64 %0, {%1, %2};" : "=l"(r) : "f"(v), "f"(v));
    return r;
}
__device__ __forceinline__ void unpack2(u64 v, float& lo, float& hi) {
    asm("mov.b64 {%0, %1}, %2;" : "=f"(lo), "=f"(hi) : "l"(v));
}

// ============================================================================
// K1: z[b,o,n] = Σ_c W[o,c]·x[b,c,n].  Tile 64o × 128n, 256 threads,
// 2 CTAs/SM (64KB smem) so prologue/epilogue overlap compute across CTAs.
// Warp w owns o∈[8w,8w+8) -> W operands are BROADCAST LDS; lane owns 4
// consecutive n (1 LDS.128 per c). 16 FFMA2 per lane per c.
// ============================================================================
__global__ __launch_bounds__(256, 2)
void k1_gemm(const float* __restrict__ x,
             const float* __restrict__ wvec,
             const float* __restrict__ W)
{
    extern __shared__ char sm[];
    u64*   wt2 = (u64*)sm;                  // [64][64] dup pairs (32 KB)
    float* xs  = (float*)(sm + 32768);      // [64][128]           (32 KB)
    __shared__ float sred[4];

    const int t    = threadIdx.x;
    const int tile = blockIdx.x;
    const int b    = tile >> 5;
    const int nb   = tile & 31;
    const int n0   = nb * TILE_N;

    // tanh(w)² partial for this 128-wide n-slice (warps 0-3)
    if (t < 128) {
        float vv = tanhf(wvec[b * NN + n0 + t]);
        vv = fmaxf(vv, 0.f);
        float sp = vv * vv;
        #pragma unroll
        for (int off = 16; off > 0; off >>= 1)
            sp += __shfl_xor_sync(0xFFFFFFFFu, sp, off);
        if ((t & 31) == 0) sred[t >> 5] = sp;
    }

    // Load W dup-packed (transposed): wt2[c][o] = {W[o,c], W[o,c]}
    #pragma unroll
    for (int i = 0; i < 16; i++) {
        int idx = i * 256 + t;
        wt2[(idx & 63) * 64 + (idx >> 6)] = packdup(W[idx]);
    }
    // Load x tile: 64 c-rows × 32 float4
    const float4* x4 = (const float4*)(x + ((size_t)b * CC) * NN + n0);
    #pragma unroll
    for (int i = 0; i < 8; i++) {
        int idx = i * 256 + t;
        int c = idx >> 5, j = idx & 31;
        ((float4*)(xs + c * TILE_N))[j] = x4[c * (NN / 4) + j];
    }
    __syncthreads();
    if (t == 0) g_spart[tile] = (sred[0] + sred[1]) + (sred[2] + sred[3]);

    const int wid = t >> 5, lane = t & 31;
    const int o0 = wid * 8;
    const float* xbase = xs + lane * 4;

    u64 acc[8][2];
    #pragma unroll
    for (int i = 0; i < 8; i++) { acc[i][0] = 0ull; acc[i][1] = 0ull; }

    #pragma unroll 4
    for (int c = 0; c < 64; c++) {
        const u64* wrow = wt2 + c * 64 + o0;
        ulonglong2 w01 = *(const ulonglong2*)(wrow);      // broadcast
        ulonglong2 w23 = *(const ulonglong2*)(wrow + 2);
        ulonglong2 w45 = *(const ulonglong2*)(wrow + 4);
        ulonglong2 w67 = *(const ulonglong2*)(wrow + 6);
        ulonglong2 xv  = *(const ulonglong2*)(xbase + c * TILE_N);
        u64 wv[8] = {w01.x, w01.y, w23.x, w23.y, w45.x, w45.y, w67.x, w67.y};
        #pragma unroll
        for (int i = 0; i < 8; i++) {
            acc[i][0] = ffma2(wv[i], xv.x, acc[i][0]);
            acc[i][1] = ffma2(wv[i], xv.y, acc[i][1]);
        }
    }

    // Write z + per-o stats (full-warp reduce over the 128 n's)
    #pragma unroll
    for (int i = 0; i < 8; i++) {
        const int o = o0 + i;
        float* zo = g_z + ((size_t)(b * CC + o)) * NN + n0 + lane * 4;
        ulonglong2 p; p.x = acc[i][0]; p.y = acc[i][1];
        *(ulonglong2*)zo = p;

        float v0, v1, v2, v3;
        unpack2(acc[i][0], v0, v1);
        unpack2(acc[i][1], v2, v3);
        float s = (v0 + v1) + (v2 + v3);
        float q = fmaf(v0, v0, fmaf(v1, v1, fmaf(v2, v2, v3 * v3)));
        #pragma unroll
        for (int off = 16; off > 0; off >>= 1) {
            s += __shfl_xor_sync(0xFFFFFFFFu, s, off);
            q += __shfl_xor_sync(0xFFFFFFFFu, q, off);
        }
        if (lane == 0) {
            g_psum[(b * CC + o) * NTB + nb] = s;
            g_psq [(b * CC + o) * NTB + nb] = q;
        }
    }
}

// ============================================================================
// K2: reduce partials -> per-(b,o) scale/bias. One block, 512 threads.
// ============================================================================
__global__ __launch_bounds__(512)
void k2_finalize(const float* __restrict__ conv_b,
                 const float* __restrict__ gamma,
                 const float* __restrict__ beta)
{
    __shared__ float s_sh[BB];
    __shared__ float zZ[BB*CC], zQ[BB*CC];
    const int t = threadIdx.x;

    // s_b: warp w reduces batch w's 32 contiguous tile partials (t<256)
    if (t < 256) {
        const int w = t >> 5, l = t & 31;
        float sp = g_spart[w * NTB + l];
        #pragma unroll
        for (int off = 16; off > 0; off >>= 1)
            sp += __shfl_xor_sync(0xFFFFFFFFu, sp, off);
        if (l == 0) s_sh[w] = sp;
    }

    // Z,Q: thread t reduces (b,o)=t's 32 contiguous partials (float4 x8 each)
    {
        const float4* p4 = (const float4*)(g_psum + t * NTB);
        const float4* q4 = (const float4*)(g_psq  + t * NTB);
        float Z = 0.f, Q = 0.f;
        #pragma unroll
        for (int i = 0; i < NTB / 4; i++) {
            float4 a = p4[i], c = q4[i];
            Z += (a.x + a.y) + (a.z + a.w);
            Q += (c.x + c.y) + (c.z + c.w);
        }
        zZ[t] = Z; zQ[t] = Q;
    }
    __syncthreads();

    if (t < CC) {
        const int o = t;
        float cb = conv_b[o];
        float alpha[BB], offv[BB];
        float mean_acc = 0.f, sq_acc = 0.f;
        #pragma unroll
        for (int bb = 0; bb < BB; bb++) {
            float s = s_sh[bb];
            float a = 1.f / (1.f + (float)NN * s);
            float Z = zZ[bb * CC + o];
            float Q = zQ[bb * CC + o];
            float off = a * s * Z + cb;
            alpha[bb] = a; offv[bb] = off;
            mean_acc += a * Z + (float)NN * off;
            sq_acc   += a * a * Q + 2.f * a * off * Z + (float)NN * off * off;
        }
        const float inv_cnt = 1.f / (float)(BB * NN);
        float mean = mean_acc * inv_cnt;
        float var  = sq_acc * inv_cnt - mean * mean;
        float invstd = rsqrtf(var + 1e-5f);
        float g  = gamma[o] * invstd;
        float be = beta[o];
        #pragma unroll
        for (int bb = 0; bb < BB; bb++) {
            g_scale[bb * CC + o] = alpha[bb] * g;
            g_bias [bb * CC + o] = (offv[bb] - mean) * g + be;
        }
    }
}

// ============================================================================
// K3: pure stream. One block per (b,o) row; uniform scale/bias; 4 indep f4.
// ============================================================================
__global__ __launch_bounds__(256)
void k3_epilogue(float* __restrict__ out)
{
    const int row = blockIdx.x;              // 512 rows of 4096 floats
    const float sc = g_scale[row];
    const float bi = g_bias[row];
    const float4* z4 = (const float4*)(g_z + (size_t)row * NN);
    float4* o4 = (float4*)(out + (size_t)row * NN);
    const int t = threadIdx.x;

    float4 v[4];
    #pragma unroll
    for (int i = 0; i < 4; i++) v[i] = z4[t + i * 256];
    #pragma unroll
    for (int i = 0; i < 4; i++) {
        float4 r;
        r.x = fmaxf(fmaf(sc, v[i].x, bi), 0.f);
        r.y = fmaxf(fmaf(sc, v[i].y, bi), 0.f);
        r.z = fmaxf(fmaf(sc, v[i].z, bi), 0.f);
        r.w = fmaxf(fmaf(sc, v[i].w, bi), 0.f);
        o4[t + i * 256] = r;
    }
}

extern "C" void kernel_launch(void* const* d_in, const int* in_sizes, int n_in,
                              void* d_out, int out_size) {
    const float* x      = (const float*)d_in[0];  // [8,64,4096,1]
    const float* w      = (const float*)d_in[1];  // [8,4096]
    const float* conv_w = (const float*)d_in[2];  // [64,64,1,1]
    const float* conv_b = (const float*)d_in[3];  // [64]
    const float* gamma  = (const float*)d_in[4];  // [64]
    const float* beta   = (const float*)d_in[5];  // [64]
    float* out = (float*)d_out;

    cudaFuncSetAttribute(k1_gemm,
                         cudaFuncAttributeMaxDynamicSharedMemorySize, 65536);
    k1_gemm<<<TILES, 256, 65536>>>(x, w, conv_w);
    k2_finalize<<<1, 512>>>(conv_b, gamma, beta);
    k3_epilogue<<<BB * CC, 256>>>(out);
}